// round 1
// baseline (speedup 1.0000x reference)
#include <cuda_runtime.h>
#include <math.h>

#define BB 128
#define TT 2048
#define HH 200
#define H4 800
#define NSTEPS 5
#define TTILE 64   // t rows per block in scores kernel

// scratch (no cudaMalloc allowed)
__device__ float g_qproj[BB * HH];
__device__ float g_hpre[BB * H4];
__device__ float g_scores[BB * TT];
__device__ float g_ctx[BB * HH];

__device__ __forceinline__ float sigf(float x) { return 1.f / (1.f + expf(-x)); }

// ---------------------------------------------------------------------------
// K1: q_proj[b,h] = h0[b]·Wa[h] + ba[h];  h_pre[b,j] = h0[b]·W_hh[j] + b_hh[j]
// ---------------------------------------------------------------------------
__global__ void k1_proj(const float* __restrict__ h0, const float* __restrict__ Wa,
                        const float* __restrict__ ba, const float* __restrict__ Whh,
                        const float* __restrict__ bhh) {
    int b = blockIdx.x, tid = threadIdx.x;
    __shared__ float h0s[HH];
    if (tid < HH) h0s[tid] = h0[b * HH + tid];
    __syncthreads();
    for (int j = tid; j < HH; j += blockDim.x) {
        const float4* w = (const float4*)(Wa + j * HH);
        float s = ba[j];
#pragma unroll 5
        for (int k = 0; k < HH / 4; k++) {
            float4 wv = w[k];
            const float* hp = &h0s[k * 4];
            s = fmaf(wv.x, hp[0], s); s = fmaf(wv.y, hp[1], s);
            s = fmaf(wv.z, hp[2], s); s = fmaf(wv.w, hp[3], s);
        }
        g_qproj[b * HH + j] = s;
    }
    for (int j = tid; j < H4; j += blockDim.x) {
        const float4* w = (const float4*)(Whh + j * HH);
        float s = bhh[j];
#pragma unroll 5
        for (int k = 0; k < HH / 4; k++) {
            float4 wv = w[k];
            const float* hp = &h0s[k * 4];
            s = fmaf(wv.x, hp[0], s); s = fmaf(wv.y, hp[1], s);
            s = fmaf(wv.z, hp[2], s); s = fmaf(wv.w, hp[3], s);
        }
        g_hpre[b * H4 + j] = s;
    }
}

// ---------------------------------------------------------------------------
// K2: fused scores[b,t] = Va · tanh(q_proj[b] + enc[b,t]@Ua.T + bua) + bva
// Block tile: 64 t x 200 h, full Ua staged in SMEM, 8x8 register micro-tile.
// k_proj tensor (210MB) is never materialized.
// ---------------------------------------------------------------------------
__global__ __launch_bounds__(256, 1)
void k2_scores(const float* __restrict__ enc, const float* __restrict__ Ua,
               const float* __restrict__ bua, const float* __restrict__ Va,
               const float* __restrict__ bva) {
    extern __shared__ float sm[];
    float* Ua_s  = sm;                 // 200*200 = 40000 floats
    float* enc_s = sm + 40000;         // 64*200  = 12800 floats
    float* part  = sm + 52800;         // 64*25   = 1600 floats

    const int b = blockIdx.y;
    const int t0 = blockIdx.x * TTILE;
    const int tid = threadIdx.x;

    // stage Ua (coalesced float4 straight copy, row-major kept)
    {
        float4* dst = (float4*)Ua_s;
        const float4* src = (const float4*)Ua;
        for (int i = tid; i < (HH * HH) / 4; i += 256) dst[i] = src[i];
    }
    // stage enc tile
    {
        float4* dst = (float4*)enc_s;
        const float4* src = (const float4*)(enc + (size_t)(b * TT + t0) * HH);
        for (int i = tid; i < (TTILE * HH) / 4; i += 256) dst[i] = src[i];
    }
    __syncthreads();

    // 200 compute threads: 8 t-groups(x8 rows) x 25 h-groups(x8 cols)
    if (tid < 200) {
        const int tt = tid / 25, th = tid % 25;
        const int tb = tt * 8, hb = th * 8;

        float acc[8][8];
#pragma unroll
        for (int i = 0; i < 8; i++)
#pragma unroll
            for (int j = 0; j < 8; j++) acc[i][j] = 0.f;

        for (int k = 0; k < HH; k += 4) {
            float4 av[8];
#pragma unroll
            for (int i = 0; i < 8; i++)
                av[i] = *(const float4*)&enc_s[(tb + i) * HH + k];
#pragma unroll
            for (int j = 0; j < 8; j++) {
                float4 bv = *(const float4*)&Ua_s[(hb + j) * HH + k];
#pragma unroll
                for (int i = 0; i < 8; i++) {
                    acc[i][j] = fmaf(av[i].x, bv.x, acc[i][j]);
                    acc[i][j] = fmaf(av[i].y, bv.y, acc[i][j]);
                    acc[i][j] = fmaf(av[i].z, bv.z, acc[i][j]);
                    acc[i][j] = fmaf(av[i].w, bv.w, acc[i][j]);
                }
            }
        }

        // epilogue: tanh + Va partial reduction (8 h per thread)
        float qp[8], bu[8], va[8];
#pragma unroll
        for (int j = 0; j < 8; j++) {
            qp[j] = g_qproj[b * HH + hb + j];
            bu[j] = bua[hb + j];
            va[j] = Va[hb + j];
        }
#pragma unroll
        for (int i = 0; i < 8; i++) {
            float s = 0.f;
#pragma unroll
            for (int j = 0; j < 8; j++)
                s = fmaf(va[j], tanhf(acc[i][j] + qp[j] + bu[j]), s);
            part[(tb + i) * 25 + th] = s;
        }
    }
    __syncthreads();

    if (tid < TTILE) {
        float s = bva[0];
#pragma unroll
        for (int m = 0; m < 25; m++) s += part[tid * 25 + m];
        g_scores[b * TT + t0 + tid] = s;
    }
}

// ---------------------------------------------------------------------------
// K3: softmax over T per batch + context[b,h] = sum_t attn * enc[b,t,h]
// ---------------------------------------------------------------------------
__global__ void k3_softmax_ctx(const float* __restrict__ enc) {
    const int b = blockIdx.x, tid = threadIdx.x;
    __shared__ float att[TT];
    __shared__ float red[256];

    float lmax = -1e30f;
    for (int t = tid; t < TT; t += 256) {
        float v = g_scores[b * TT + t];
        att[t] = v;
        lmax = fmaxf(lmax, v);
    }
    red[tid] = lmax;
    __syncthreads();
    for (int s = 128; s > 0; s >>= 1) {
        if (tid < s) red[tid] = fmaxf(red[tid], red[tid + s]);
        __syncthreads();
    }
    float smax = red[0];
    __syncthreads();

    float lsum = 0.f;
    for (int t = tid; t < TT; t += 256) {
        float e = expf(att[t] - smax);
        att[t] = e;
        lsum += e;
    }
    red[tid] = lsum;
    __syncthreads();
    for (int s = 128; s > 0; s >>= 1) {
        if (tid < s) red[tid] += red[tid + s];
        __syncthreads();
    }
    float inv = 1.f / red[0];
    __syncthreads();

    if (tid < HH) {
        const float* ep = enc + (size_t)b * TT * HH + tid;
        float a = 0.f;
#pragma unroll 8
        for (int t = 0; t < TT; t++) a = fmaf(att[t], ep[(size_t)t * HH], a);
        g_ctx[b * HH + tid] = a * inv;
    }
}

// ---------------------------------------------------------------------------
// K4: decode. gbase = ctx@W_ih[:,1:].T + b_ih + h_pre (constant), then 5 tiny
// steps: gates = gbase + x*W_ih[:,0] -> LSTM -> relu -> 200->100->50->1 MLP.
// ---------------------------------------------------------------------------
__global__ void k4_decode(const float* __restrict__ x0, const float* __restrict__ c0,
                          const float* __restrict__ W_ih, const float* __restrict__ b_ih,
                          const float* __restrict__ W1, const float* __restrict__ b1,
                          const float* __restrict__ W2, const float* __restrict__ b2,
                          const float* __restrict__ W3, const float* __restrict__ b3,
                          float* __restrict__ out) {
    const int b = blockIdx.x, tid = threadIdx.x;
    __shared__ float ctx_s[HH];
    __shared__ float gbase[H4];
    __shared__ float hbuf[HH];
    __shared__ float o1[100];
    __shared__ float o2[50];
    __shared__ float xs;

    if (tid < HH) ctx_s[tid] = g_ctx[b * HH + tid];
    if (tid == 0) xs = x0[b];
    __syncthreads();

    for (int j = tid; j < H4; j += blockDim.x) {
        float s = b_ih[j] + g_hpre[b * H4 + j];
        const float* wr = W_ih + (size_t)j * 201 + 1;
#pragma unroll 8
        for (int k = 0; k < HH; k++) s = fmaf(ctx_s[k], wr[k], s);
        gbase[j] = s;
    }
    __syncthreads();

    for (int step = 0; step < NSTEPS; step++) {
        if (tid < HH) {
            int h = tid;
            float x = xs;
            float gi = gbase[h]       + x * W_ih[(size_t)h * 201];
            float gf = gbase[200 + h] + x * W_ih[(size_t)(200 + h) * 201];
            float gg = gbase[400 + h] + x * W_ih[(size_t)(400 + h) * 201];
            float go = gbase[600 + h] + x * W_ih[(size_t)(600 + h) * 201];
            float c_new = sigf(gf) * c0[b * HH + h] + sigf(gi) * tanhf(gg);
            float hn = sigf(go) * tanhf(c_new);
            hbuf[h] = fmaxf(hn, 0.f);
        }
        __syncthreads();
        if (tid < 100) {
            float s = b1[tid];
            const float* wr = W1 + (size_t)tid * HH;
#pragma unroll 8
            for (int k = 0; k < HH; k++) s = fmaf(hbuf[k], wr[k], s);
            o1[tid] = fmaxf(s, 0.f);
        }
        __syncthreads();
        if (tid < 50) {
            float s = b2[tid];
            const float* wr = W2 + (size_t)tid * 100;
#pragma unroll 4
            for (int k = 0; k < 100; k++) s = fmaf(o1[k], wr[k], s);
            o2[tid] = fmaxf(s, 0.f);
        }
        __syncthreads();
        if (tid == 0) {
            float y = b3[0];
#pragma unroll
            for (int k = 0; k < 50; k++) y = fmaf(o2[k], W3[k], y);
            out[b * NSTEPS + step] = y;
            xs = y;
        }
        __syncthreads();
    }
}

// ---------------------------------------------------------------------------
extern "C" void kernel_launch(void* const* d_in, const int* in_sizes, int n_in,
                              void* d_out, int out_size) {
    const float* x    = (const float*)d_in[0];
    const float* h0   = (const float*)d_in[1];
    const float* c0   = (const float*)d_in[2];
    const float* enc  = (const float*)d_in[3];
    const float* Wa   = (const float*)d_in[4];
    const float* ba   = (const float*)d_in[5];
    const float* Ua   = (const float*)d_in[6];
    const float* bua  = (const float*)d_in[7];
    const float* Va   = (const float*)d_in[8];
    const float* bva  = (const float*)d_in[9];
    const float* W_ih = (const float*)d_in[10];
    const float* W_hh = (const float*)d_in[11];
    const float* b_ih = (const float*)d_in[12];
    const float* b_hh = (const float*)d_in[13];
    const float* W1   = (const float*)d_in[14];
    const float* b1   = (const float*)d_in[15];
    const float* W2   = (const float*)d_in[16];
    const float* b2   = (const float*)d_in[17];
    const float* W3   = (const float*)d_in[18];
    const float* b3   = (const float*)d_in[19];
    float* out = (float*)d_out;

    const int smem2 = (40000 + 12800 + 1600) * sizeof(float);  // 217600 B
    cudaFuncSetAttribute(k2_scores, cudaFuncAttributeMaxDynamicSharedMemorySize, smem2);

    k1_proj<<<BB, 256>>>(h0, Wa, ba, W_hh, b_hh);
    k2_scores<<<dim3(TT / TTILE, BB), 256, smem2>>>(enc, Ua, bua, Va, bva);
    k3_softmax_ctx<<<BB, 256>>>(enc);
    k4_decode<<<BB, 256>>>(x, c0, W_ih, b_ih, W1, b1, W2, b2, W3, b3, out);
}

// round 3
// speedup vs baseline: 1.1493x; 1.1493x over previous
#include <cuda_runtime.h>
#include <math.h>
#include <stdint.h>

#define BB 128
#define TT 2048
#define HH 200
#define H4 800
#define NSTEPS 5
#define TTILE 64          // t rows per block in scores kernel
#define NKC 25            // k chunks of 8 (200/8)
#define NNT 25            // n tiles of 8 (200/8)

// scratch (no cudaMalloc allowed)
__device__ float g_qproj[BB * HH];
__device__ float g_hpre[BB * H4];
__device__ float g_scores[BB * TT];
__device__ float g_ctxp[8 * BB * HH];   // [chunk][b][h] context partials

__device__ __forceinline__ float sigf(float x) { return 1.f / (1.f + expf(-x)); }

__device__ __forceinline__ uint32_t f2tf32(float x) {
    uint32_t r;
    asm("cvt.rna.tf32.f32 %0, %1;" : "=r"(r) : "f"(x));
    return r;
}

__device__ __forceinline__ void mma_tf32(float* c, uint4 a, uint2 b) {
    asm volatile(
        "mma.sync.aligned.m16n8k8.row.col.f32.tf32.tf32.f32 "
        "{%0,%1,%2,%3}, {%4,%5,%6,%7}, {%8,%9}, {%0,%1,%2,%3};\n"
        : "+f"(c[0]), "+f"(c[1]), "+f"(c[2]), "+f"(c[3])
        : "r"(a.x), "r"(a.y), "r"(a.z), "r"(a.w), "r"(b.x), "r"(b.y));
}

__device__ __forceinline__ float warp_reduce(float v) {
#pragma unroll
    for (int m = 16; m > 0; m >>= 1) v += __shfl_xor_sync(0xffffffffu, v, m);
    return v;
}

// ---------------------------------------------------------------------------
// K1: q_proj[b,h] = h0[b]·Wa[h] + ba[h];  h_pre[b,j] = h0[b]·W_hh[j] + b_hh[j]
// ---------------------------------------------------------------------------
__global__ void k1_proj(const float* __restrict__ h0, const float* __restrict__ Wa,
                        const float* __restrict__ ba, const float* __restrict__ Whh,
                        const float* __restrict__ bhh) {
    int b = blockIdx.x, tid = threadIdx.x;
    __shared__ float h0s[HH];
    if (tid < HH) h0s[tid] = h0[b * HH + tid];
    __syncthreads();
    for (int j = tid; j < HH; j += blockDim.x) {
        const float4* w = (const float4*)(Wa + j * HH);
        float s0 = 0.f, s1 = 0.f, s2 = 0.f, s3 = 0.f;
#pragma unroll 5
        for (int k = 0; k < HH / 4; k++) {
            float4 wv = w[k];
            const float* hp = &h0s[k * 4];
            s0 = fmaf(wv.x, hp[0], s0); s1 = fmaf(wv.y, hp[1], s1);
            s2 = fmaf(wv.z, hp[2], s2); s3 = fmaf(wv.w, hp[3], s3);
        }
        g_qproj[b * HH + j] = s0 + s1 + s2 + s3 + ba[j];
    }
    for (int j = tid; j < H4; j += blockDim.x) {
        const float4* w = (const float4*)(Whh + j * HH);
        float s0 = 0.f, s1 = 0.f, s2 = 0.f, s3 = 0.f;
#pragma unroll 5
        for (int k = 0; k < HH / 4; k++) {
            float4 wv = w[k];
            const float* hp = &h0s[k * 4];
            s0 = fmaf(wv.x, hp[0], s0); s1 = fmaf(wv.y, hp[1], s1);
            s2 = fmaf(wv.z, hp[2], s2); s3 = fmaf(wv.w, hp[3], s3);
        }
        g_hpre[b * H4 + j] = s0 + s1 + s2 + s3 + bhh[j];
    }
}

// ---------------------------------------------------------------------------
// K2: tensor-core (tf32 mma.sync) fused scores kernel.
// S[t,h] = enc[b,t,:]·Ua[h,:] ; scores = Va·tanh(S + qp + bua) + bva.
// Ua and enc tile staged in SMEM in MMA *fragment layout*, tf32-converted.
// Warps: 2 m-groups (32 rows each) x 4 n-groups (6-7 n-tiles each).
// ---------------------------------------------------------------------------
__global__ __launch_bounds__(256, 1)
void k2_scores(const float* __restrict__ enc, const float* __restrict__ Ua,
               const float* __restrict__ bua, const float* __restrict__ Va,
               const float* __restrict__ bva) {
    extern __shared__ uint32_t smu[];
    uint32_t* Bs = smu;                       // 25nt*25c*32lane*2 = 40000 u32
    uint32_t* As = smu + 40000;               // 4mt*25c*32lane*4  = 12800 u32
    float*   part = (float*)(smu + 52800);    // 64 x 16 floats

    const int b  = blockIdx.y;
    const int t0 = blockIdx.x * TTILE;
    const int tid = threadIdx.x;

    // ---- stage Ua into B-fragment layout (tf32) ----
    for (int idx = tid; idx < HH * HH; idx += 256) {
        int h = idx / HH, k = idx % HH;
        int nt = h >> 3, gid = h & 7;
        int c = k >> 3, kk = k & 7;
        int tq = kk & 3, hi = kk >> 2;
        int lane = gid * 4 + tq;
        Bs[((nt * NKC + c) * 32 + lane) * 2 + hi] = f2tf32(Ua[idx]);
    }
    // ---- stage enc tile into A-fragment layout (tf32) ----
    {
        const float* ep = enc + (size_t)(b * TT + t0) * HH;
        for (int idx = tid; idx < TTILE * HH; idx += 256) {
            int t = idx / HH, k = idx % HH;
            int mt = t >> 4, r = t & 15;
            int gid = r & 7, half = r >> 3;
            int c = k >> 3, kk = k & 7;
            int tq = kk & 3, hi = kk >> 2;
            int lane = gid * 4 + tq;
            As[((mt * NKC + c) * 32 + lane) * 4 + hi * 2 + half] = f2tf32(ep[idx]);
        }
    }
    __syncthreads();

    const int lane = tid & 31;
    const int w = tid >> 5;
    const int mg = w >> 2;          // 0..1 : rows mg*32 .. mg*32+31
    const int ng = w & 3;           // 0..3
    const int ns = (ng * NNT) >> 2;
    const int ne = ((ng + 1) * NNT) >> 2;   // 6,6,6,7 tiles
    const int mt0 = mg * 2;

    float acc[2][7][4];
#pragma unroll
    for (int i = 0; i < 2; i++)
#pragma unroll
        for (int j = 0; j < 7; j++)
#pragma unroll
            for (int e = 0; e < 4; e++) acc[i][j][e] = 0.f;

    const uint4* Af = (const uint4*)As;
    const uint2* Bf = (const uint2*)Bs;

    for (int c = 0; c < NKC; c++) {
        uint4 a0 = Af[(mt0 * NKC + c) * 32 + lane];
        uint4 a1 = Af[((mt0 + 1) * NKC + c) * 32 + lane];
        for (int nt = ns; nt < ne; nt++) {
            uint2 bv = Bf[(nt * NKC + c) * 32 + lane];
            mma_tf32(acc[0][nt - ns], a0, bv);
            mma_tf32(acc[1][nt - ns], a1, bv);
        }
    }

    // ---- epilogue: tanh + Va partial reduction ----
    const int gid = lane >> 2, q4 = lane & 3;
    float p[2][2] = {{0.f, 0.f}, {0.f, 0.f}};
    for (int jn = 0; jn < ne - ns; jn++) {
        int nt = ns + jn;
        int h0 = nt * 8 + 2 * q4, h1 = h0 + 1;
        float qb0 = g_qproj[b * HH + h0] + bua[h0], va0 = Va[h0];
        float qb1 = g_qproj[b * HH + h1] + bua[h1], va1 = Va[h1];
#pragma unroll
        for (int i = 0; i < 2; i++) {
            p[i][0] += va0 * tanhf(acc[i][jn][0] + qb0) + va1 * tanhf(acc[i][jn][1] + qb1);
            p[i][1] += va0 * tanhf(acc[i][jn][2] + qb0) + va1 * tanhf(acc[i][jn][3] + qb1);
        }
    }
#pragma unroll
    for (int i = 0; i < 2; i++) {
        int r0 = mg * 32 + i * 16 + gid;
        part[r0 * 16 + ng * 4 + q4] = p[i][0];
        part[(r0 + 8) * 16 + ng * 4 + q4] = p[i][1];
    }
    __syncthreads();

    if (tid < TTILE) {
        float s = bva[0];
#pragma unroll
        for (int m = 0; m < 16; m++) s += part[tid * 16 + m];
        g_scores[b * TT + t0 + tid] = s;
    }
}

// ---------------------------------------------------------------------------
// K3a: softmax over T per batch; write normalized attn back into g_scores.
// ---------------------------------------------------------------------------
__global__ void k3a_softmax() {
    const int b = blockIdx.x, tid = threadIdx.x;
    __shared__ float red[256];

    float lmax = -1e30f;
    for (int t = tid; t < TT; t += 256) lmax = fmaxf(lmax, g_scores[b * TT + t]);
    red[tid] = lmax;
    __syncthreads();
    for (int s = 128; s > 0; s >>= 1) {
        if (tid < s) red[tid] = fmaxf(red[tid], red[tid + s]);
        __syncthreads();
    }
    float smax = red[0];
    __syncthreads();

    float lsum = 0.f;
    for (int t = tid; t < TT; t += 256) lsum += expf(g_scores[b * TT + t] - smax);
    red[tid] = lsum;
    __syncthreads();
    for (int s = 128; s > 0; s >>= 1) {
        if (tid < s) red[tid] += red[tid + s];
        __syncthreads();
    }
    float inv = 1.f / red[0];
    __syncthreads();

    for (int t = tid; t < TT; t += 256)
        g_scores[b * TT + t] = expf(g_scores[b * TT + t] - smax) * inv;
}

// ---------------------------------------------------------------------------
// K3b: context partials. grid (8 chunks, B). Each block: 256 t's.
// 50 float4-h-groups x 5 t-sublanes for bandwidth saturation.
// ---------------------------------------------------------------------------
__global__ __launch_bounds__(256)
void k3b_ctx(const float* __restrict__ enc) {
    const int ch = blockIdx.x, b = blockIdx.y, tid = threadIdx.x;
    __shared__ float atts[256];
    __shared__ float pbuf[5 * HH];

    atts[tid] = g_scores[b * TT + ch * 256 + tid];
    __syncthreads();

    const int g = tid % 50, sub = tid / 50;
    if (sub < 5) {
        float4 a = make_float4(0.f, 0.f, 0.f, 0.f);
        const float* base = enc + (size_t)(b * TT + ch * 256) * HH + g * 4;
        for (int t = sub; t < 256; t += 5) {
            float w = atts[t];
            float4 e = *(const float4*)(base + (size_t)t * HH);
            a.x = fmaf(w, e.x, a.x); a.y = fmaf(w, e.y, a.y);
            a.z = fmaf(w, e.z, a.z); a.w = fmaf(w, e.w, a.w);
        }
        *(float4*)&pbuf[sub * HH + g * 4] = a;
    }
    __syncthreads();

    if (tid < HH) {
        float s = 0.f;
#pragma unroll
        for (int u = 0; u < 5; u++) s += pbuf[u * HH + tid];
        g_ctxp[(ch * BB + b) * HH + tid] = s;
    }
}

// ---------------------------------------------------------------------------
// K4: decode. gbase = ctx@W_ih[:,1:].T + b_ih + h_pre (constant); then 5 tiny
// steps with SMEM-resident MLP weights and warp-cooperative matvecs.
// ---------------------------------------------------------------------------
__global__ __launch_bounds__(256)
void k4_decode(const float* __restrict__ x0, const float* __restrict__ c0,
               const float* __restrict__ W_ih, const float* __restrict__ b_ih,
               const float* __restrict__ W1, const float* __restrict__ b1,
               const float* __restrict__ W2, const float* __restrict__ b2,
               const float* __restrict__ W3, const float* __restrict__ b3,
               float* __restrict__ out) {
    extern __shared__ float sm4[];
    float* W1s = sm4;              // 100*200 = 20000
    float* W2s = sm4 + 20000;      // 50*100  = 5000
    float* W3s = sm4 + 25000;      // 50
    float* ctx_s = sm4 + 25056;    // 200
    float* gbase = sm4 + 25256;    // 800
    float* hbuf = sm4 + 26056;     // 200
    float* o1 = sm4 + 26256;       // 104
    float* o2 = sm4 + 26360;       // 56
    float* xsp = sm4 + 26416;      // 1

    const int b = blockIdx.x, tid = threadIdx.x;
    const int w = tid >> 5, lane = tid & 31;

    // stage MLP weights (coalesced float4)
    {
        const float4* s1 = (const float4*)W1;
        float4* d1 = (float4*)W1s;
        for (int i = tid; i < 5000; i += 256) d1[i] = s1[i];
        const float4* s2 = (const float4*)W2;
        float4* d2 = (float4*)W2s;
        for (int i = tid; i < 1250; i += 256) d2[i] = s2[i];
        if (tid < 50) W3s[tid] = W3[tid];
    }
    if (tid < HH) {
        float s = 0.f;
#pragma unroll
        for (int c = 0; c < 8; c++) s += g_ctxp[(c * BB + b) * HH + tid];
        ctx_s[tid] = s;
    }
    if (tid == 0) xsp[0] = x0[b];
    __syncthreads();

    // gbase: each thread streams its own W_ih row(s); 4 independent chains
    for (int j = tid; j < H4; j += 256) {
        const float* wr = W_ih + (size_t)j * 201 + 1;
        float s0 = 0.f, s1 = 0.f, s2 = 0.f, s3 = 0.f;
#pragma unroll 8
        for (int k = 0; k < HH; k += 4) {
            s0 = fmaf(wr[k], ctx_s[k], s0);
            s1 = fmaf(wr[k + 1], ctx_s[k + 1], s1);
            s2 = fmaf(wr[k + 2], ctx_s[k + 2], s2);
            s3 = fmaf(wr[k + 3], ctx_s[k + 3], s3);
        }
        gbase[j] = s0 + s1 + s2 + s3 + b_ih[j] + g_hpre[b * H4 + j];
    }
    __syncthreads();

    for (int step = 0; step < NSTEPS; step++) {
        float x = xsp[0];
        if (tid < HH) {
            int h = tid;
            float gi = gbase[h]       + x * W_ih[(size_t)h * 201];
            float gf = gbase[200 + h] + x * W_ih[(size_t)(200 + h) * 201];
            float gg = gbase[400 + h] + x * W_ih[(size_t)(400 + h) * 201];
            float go = gbase[600 + h] + x * W_ih[(size_t)(600 + h) * 201];
            float c_new = sigf(gf) * c0[b * HH + h] + sigf(gi) * tanhf(gg);
            hbuf[h] = fmaxf(sigf(go) * tanhf(c_new), 0.f);
        }
        __syncthreads();

        // layer1: 100 outputs, warp-per-output
        for (int o = w; o < 100; o += 8) {
            float s = 0.f;
            const float* wr = W1s + o * HH;
            for (int k = lane; k < HH; k += 32) s = fmaf(wr[k], hbuf[k], s);
            s = warp_reduce(s);
            if (lane == 0) o1[o] = fmaxf(s + b1[o], 0.f);
        }
        __syncthreads();

        // layer2: 50 outputs
        for (int o = w; o < 50; o += 8) {
            float s = 0.f;
            const float* wr = W2s + o * 100;
            for (int k = lane; k < 100; k += 32) s = fmaf(wr[k], o1[k], s);
            s = warp_reduce(s);
            if (lane == 0) o2[o] = fmaxf(s + b2[o], 0.f);
        }
        __syncthreads();

        // layer3: single output
        if (w == 0) {
            float s = 0.f;
            for (int k = lane; k < 50; k += 32) s = fmaf(W3s[k], o2[k], s);
            s = warp_reduce(s);
            if (lane == 0) {
                float y = s + b3[0];
                out[b * NSTEPS + step] = y;
                xsp[0] = y;
            }
        }
        __syncthreads();
    }
}

// ---------------------------------------------------------------------------
extern "C" void kernel_launch(void* const* d_in, const int* in_sizes, int n_in,
                              void* d_out, int out_size) {
    const float* x    = (const float*)d_in[0];
    const float* h0   = (const float*)d_in[1];
    const float* c0   = (const float*)d_in[2];
    const float* enc  = (const float*)d_in[3];
    const float* Wa   = (const float*)d_in[4];
    const float* ba   = (const float*)d_in[5];
    const float* Ua   = (const float*)d_in[6];
    const float* bua  = (const float*)d_in[7];
    const float* Va   = (const float*)d_in[8];
    const float* bva  = (const float*)d_in[9];
    const float* W_ih = (const float*)d_in[10];
    const float* W_hh = (const float*)d_in[11];
    const float* b_ih = (const float*)d_in[12];
    const float* b_hh = (const float*)d_in[13];
    const float* W1   = (const float*)d_in[14];
    const float* b1   = (const float*)d_in[15];
    const float* W2   = (const float*)d_in[16];
    const float* b2   = (const float*)d_in[17];
    const float* W3   = (const float*)d_in[18];
    const float* b3   = (const float*)d_in[19];
    float* out = (float*)d_out;

    const int smem2 = (40000 + 12800 + 1024) * sizeof(uint32_t);  // 215296 B
    cudaFuncSetAttribute(k2_scores, cudaFuncAttributeMaxDynamicSharedMemorySize, smem2);
    const int smem4 = 26420 * sizeof(float);                      // ~105.7 KB
    cudaFuncSetAttribute(k4_decode, cudaFuncAttributeMaxDynamicSharedMemorySize, smem4);

    k1_proj<<<BB, 256>>>(h0, Wa, ba, W_hh, b_hh);
    k2_scores<<<dim3(TT / TTILE, BB), 256, smem2>>>(enc, Ua, bua, Va, bva);
    k3a_softmax<<<BB, 256>>>();
    k3b_ctx<<<dim3(8, BB), 256>>>(enc);
    k4_decode<<<BB, 256, smem4>>>(x, c0, W_ih, b_ih, W1, b1, W2, b2, W3, b3, out);
}

// round 7
// speedup vs baseline: 1.8245x; 1.5875x over previous
#include <cuda_runtime.h>
#include <math.h>
#include <stdint.h>

#define BB 128
#define TT 2048
#define HH 200
#define H4 800
#define NSTEPS 5

// ---------------- scratch globals (no cudaMalloc allowed) ------------------
__device__ float g_qproj[BB * HH];
__device__ float g_hpre[BB * H4];
__device__ float g_scores[BB * TT];
__device__ float g_ctxp[8 * BB * HH];
// paired Ua: [chunk c(2)][hg(26)][k'(100)][2 x uint4] ; uint4 = Ua[h..h+3][k]
__device__ __align__(16) float4 g_uap[2 * 26 * 100 * 2];

__device__ __forceinline__ float sigf(float x) { return 1.f / (1.f + expf(-x)); }

__device__ __forceinline__ float warp_reduce(float v) {
#pragma unroll
    for (int m = 16; m > 0; m >>= 1) v += __shfl_xor_sync(0xffffffffu, v, m);
    return v;
}

__device__ __forceinline__ float tanh_fast(float x) {
    // tanh(x) = 1 - 2/(e^{2x}+1), via MUFU ex2/rcp
    float e;
    asm("ex2.approx.f32 %0, %1;" : "=f"(e) : "f"(x * 2.885390081777927f));
    float r;
    asm("rcp.approx.f32 %0, %1;" : "=f"(r) : "f"(e + 1.0f));
    return fmaf(-2.f, r, 1.f);
}

__device__ __forceinline__ uint32_t smem_u32(const void* p) {
    uint32_t a;
    asm("{ .reg .u64 t; cvta.to.shared.u64 t, %1; cvt.u32.u64 %0, t; }" : "=r"(a) : "l"(p));
    return a;
}

// packed fp32x2 FMA (B300 FFMA2 — 2 MACs/lane/instr)
#define FMA2(c, a, b) \
    asm("fma.rn.f32x2 %0, %1, %2, %0;" : "+l"(c) : "l"(a), "l"(b))
#define PACKDUP(p, v) \
    asm("mov.b64 %0, {%1, %1};" : "=l"(p) : "f"(v))
#define UNPACK2(lo, hi, p) \
    asm("mov.b64 {%0, %1}, %2;" : "=f"(lo), "=f"(hi) : "l"(p))

// ---------------------------------------------------------------------------
// KP: build paired Ua layout. pair j = (Ua[h][k], Ua[h+1][k]), h = hg*8+2j.
// uint4 (c,hg,k',jj) = floats Ua[hg*8+4jj .. +3][k],  k = c*100+k'.  hg=25 -> 0.
// ---------------------------------------------------------------------------
__global__ void kP_pack_ua(const float* __restrict__ Ua) {
    int i = blockIdx.x * 256 + threadIdx.x;
    if (i >= 10400) return;
    int c = i / 5200, rem = i % 5200;
    int hg = rem / 200, r = rem % 200;
    int k4 = r >> 1, jj = r & 1;
    int k = c * 100 + k4;
    float4 v = make_float4(0.f, 0.f, 0.f, 0.f);
    if (hg < 25) {
        int h = hg * 8 + jj * 4;
        v.x = Ua[h * HH + k];
        v.y = Ua[(h + 1) * HH + k];
        v.z = Ua[(h + 2) * HH + k];
        v.w = Ua[(h + 3) * HH + k];
    }
    g_uap[i] = v;
}

// ---------------------------------------------------------------------------
// K1: q_proj[b,h] = h0[b]·Wa[h] + ba[h];  h_pre[b,j] = h0[b]·W_hh[j] + b_hh[j]
// ---------------------------------------------------------------------------
__global__ void k1_proj(const float* __restrict__ h0, const float* __restrict__ Wa,
                        const float* __restrict__ ba, const float* __restrict__ Whh,
                        const float* __restrict__ bhh) {
    int b = blockIdx.x, tid = threadIdx.x;
    __shared__ float h0s[HH];
    if (tid < HH) h0s[tid] = h0[b * HH + tid];
    __syncthreads();
    for (int j = tid; j < HH; j += blockDim.x) {
        const float4* w = (const float4*)(Wa + j * HH);
        float s0 = 0.f, s1 = 0.f, s2 = 0.f, s3 = 0.f;
#pragma unroll 5
        for (int k = 0; k < HH / 4; k++) {
            float4 wv = w[k];
            const float* hp = &h0s[k * 4];
            s0 = fmaf(wv.x, hp[0], s0); s1 = fmaf(wv.y, hp[1], s1);
            s2 = fmaf(wv.z, hp[2], s2); s3 = fmaf(wv.w, hp[3], s3);
        }
        g_qproj[b * HH + j] = s0 + s1 + s2 + s3 + ba[j];
    }
    for (int j = tid; j < H4; j += blockDim.x) {
        const float4* w = (const float4*)(Whh + j * HH);
        float s0 = 0.f, s1 = 0.f, s2 = 0.f, s3 = 0.f;
#pragma unroll 5
        for (int k = 0; k < HH / 4; k++) {
            float4 wv = w[k];
            const float* hp = &h0s[k * 4];
            s0 = fmaf(wv.x, hp[0], s0); s1 = fmaf(wv.y, hp[1], s1);
            s2 = fmaf(wv.z, hp[2], s2); s3 = fmaf(wv.w, hp[3], s3);
        }
        g_hpre[b * H4 + j] = s0 + s1 + s2 + s3 + bhh[j];
    }
}

// ---------------------------------------------------------------------------
// K2: packed-fp32 (fma.rn.f32x2) fused scores kernel.
// Per CTA: 128 t-rows x 208 h (padded), 208 threads (tid = tg*26 + hg),
// micro-tile 16t x 8h (64 f32x2 accumulators).
// K split in 2 chunks of 100; Ua chunk staged per-iteration (pad-strided rows
// -> conflict-free LDS), enc rows padded to 201 floats (odd) so tg-boundary
// lanes hit distinct banks. scores = Va·tanh(S + qp + bua) + bva fused.
// ---------------------------------------------------------------------------
// SMEM byte offsets
#define S2_ENC  0                         // 128*201*4   = 102912
#define S2_UA   102912                    // 26*3216     = 83616
#define S2_PART 186528                    // 128*26*4    = 13312
#define S2_QPB  199840                    // 800
#define S2_VAS  200640                    // 800
#define S2_TOTAL 201440
#define UA_ROW 3216                       // 100*32 + 16 pad

__global__ __launch_bounds__(208, 1)
void k2_scores_f2(const float* __restrict__ enc,
                  const float* __restrict__ bua, const float* __restrict__ Va,
                  const float* __restrict__ bva) {
    extern __shared__ char smc[];
    float* enc_s = (float*)smc;
    float* part = (float*)(smc + S2_PART);
    float* qpb = (float*)(smc + S2_QPB);
    float* vas = (float*)(smc + S2_VAS);
    const uint32_t ua_s = smem_u32(smc) + S2_UA;

    const int b = blockIdx.y;
    const int t0 = blockIdx.x * 128;
    const int tid = threadIdx.x;
    const int tg = tid / 26, hg = tid % 26;

    // stage enc tile (rows padded to 201 floats)
    {
        const float* ep = enc + (size_t)(b * TT + t0) * HH;
        for (int i = tid; i < 128 * HH; i += 208) {
            int r = i / HH, cc = i % HH;
            enc_s[r * 201 + cc] = ep[i];
        }
    }
    if (tid < HH) {
        qpb[tid] = g_qproj[b * HH + tid] + bua[tid];
        vas[tid] = Va[tid];
    }

    uint64_t acc[16][4];
#pragma unroll
    for (int i = 0; i < 16; i++)
#pragma unroll
        for (int j = 0; j < 4; j++) acc[i][j] = 0ull;

    const float* erow = enc_s + tg * 16 * 201;
    const uint32_t uabase = ua_s + hg * UA_ROW;

    for (int c = 0; c < 2; c++) {
        __syncthreads();
        // stage Ua chunk c into pad-strided SMEM rows
        for (int i = tid; i < 5200; i += 208) {
            int shg = i / 200, r = i % 200;
            int k4 = r >> 1, jj = r & 1;
            *(float4*)(smc + S2_UA + shg * UA_ROW + k4 * 32 + jj * 16) =
                g_uap[c * 5200 + i];
        }
        __syncthreads();

        const int kofs = c * 100;
#pragma unroll 2
        for (int k = 0; k < 100; k++) {
            uint64_t P0, P1, P2, P3;
            uint32_t ua = uabase + k * 32;
            asm("ld.shared.v2.u64 {%0,%1}, [%2];" : "=l"(P0), "=l"(P1) : "r"(ua));
            asm("ld.shared.v2.u64 {%0,%1}, [%2];" : "=l"(P2), "=l"(P3) : "r"(ua + 16));
            const float* ek = erow + kofs + k;
#pragma unroll
            for (int i = 0; i < 16; i++) {
                uint64_t p;
                PACKDUP(p, ek[i * 201]);
                FMA2(acc[i][0], p, P0);
                FMA2(acc[i][1], p, P1);
                FMA2(acc[i][2], p, P2);
                FMA2(acc[i][3], p, P3);
            }
        }
    }

    // epilogue: tanh + Va partial reduction
    if (hg < 25) {
#pragma unroll
        for (int i = 0; i < 16; i++) {
            float s = 0.f;
#pragma unroll
            for (int j = 0; j < 4; j++) {
                float x, y;
                UNPACK2(x, y, acc[i][j]);
                int h0 = hg * 8 + 2 * j;
                s += vas[h0] * tanh_fast(x + qpb[h0]) +
                     vas[h0 + 1] * tanh_fast(y + qpb[h0 + 1]);
            }
            part[(tg * 16 + i) * 26 + hg] = s;
        }
    } else {
#pragma unroll
        for (int i = 0; i < 16; i++) part[(tg * 16 + i) * 26 + 25] = 0.f;
    }
    __syncthreads();

    if (tid < 128) {
        float s = bva[0];
#pragma unroll
        for (int m = 0; m < 26; m++) s += part[tid * 26 + m];
        g_scores[b * TT + t0 + tid] = s;
    }
}

// ---------------------------------------------------------------------------
// K3a: softmax over T per batch (in-place normalize g_scores)
// ---------------------------------------------------------------------------
__global__ void k3a_softmax() {
    const int b = blockIdx.x, tid = threadIdx.x;
    __shared__ float red[256];

    float lmax = -1e30f;
    for (int t = tid; t < TT; t += 256) lmax = fmaxf(lmax, g_scores[b * TT + t]);
    red[tid] = lmax;
    __syncthreads();
    for (int s = 128; s > 0; s >>= 1) {
        if (tid < s) red[tid] = fmaxf(red[tid], red[tid + s]);
        __syncthreads();
    }
    float smax = red[0];
    __syncthreads();

    float lsum = 0.f;
    for (int t = tid; t < TT; t += 256) lsum += expf(g_scores[b * TT + t] - smax);
    red[tid] = lsum;
    __syncthreads();
    for (int s = 128; s > 0; s >>= 1) {
        if (tid < s) red[tid] += red[tid + s];
        __syncthreads();
    }
    float inv = 1.f / red[0];
    __syncthreads();

    for (int t = tid; t < TT; t += 256)
        g_scores[b * TT + t] = expf(g_scores[b * TT + t] - smax) * inv;
}

// ---------------------------------------------------------------------------
// K3b: context partials (DRAM-bound, ~71% of spec)
// ---------------------------------------------------------------------------
__global__ __launch_bounds__(256)
void k3b_ctx(const float* __restrict__ enc) {
    const int ch = blockIdx.x, b = blockIdx.y, tid = threadIdx.x;
    __shared__ float atts[256];
    __shared__ float pbuf[5 * HH];

    atts[tid] = g_scores[b * TT + ch * 256 + tid];
    __syncthreads();

    const int g = tid % 50, sub = tid / 50;
    if (sub < 5) {
        float4 a = make_float4(0.f, 0.f, 0.f, 0.f);
        const float* base = enc + (size_t)(b * TT + ch * 256) * HH + g * 4;
        for (int t = sub; t < 256; t += 5) {
            float w = atts[t];
            float4 e = *(const float4*)(base + (size_t)t * HH);
            a.x = fmaf(w, e.x, a.x); a.y = fmaf(w, e.y, a.y);
            a.z = fmaf(w, e.z, a.z); a.w = fmaf(w, e.w, a.w);
        }
        *(float4*)&pbuf[sub * HH + g * 4] = a;
    }
    __syncthreads();

    if (tid < HH) {
        float s = 0.f;
#pragma unroll
        for (int u = 0; u < 5; u++) s += pbuf[u * HH + tid];
        g_ctxp[(ch * BB + b) * HH + tid] = s;
    }
}

// ---------------------------------------------------------------------------
// K4: decode (SMEM weights + warp-cooperative matvecs)
// ---------------------------------------------------------------------------
__global__ __launch_bounds__(256)
void k4_decode(const float* __restrict__ x0, const float* __restrict__ c0,
               const float* __restrict__ W_ih, const float* __restrict__ b_ih,
               const float* __restrict__ W1, const float* __restrict__ b1,
               const float* __restrict__ W2, const float* __restrict__ b2,
               const float* __restrict__ W3, const float* __restrict__ b3,
               float* __restrict__ out) {
    extern __shared__ float sm4[];
    float* W1s = sm4;              // 20000
    float* W2s = sm4 + 20000;      // 5000
    float* W3s = sm4 + 25000;      // 50
    float* ctx_s = sm4 + 25056;    // 200
    float* gbase = sm4 + 25256;    // 800
    float* hbuf = sm4 + 26056;     // 200
    float* o1 = sm4 + 26256;       // 104
    float* o2 = sm4 + 26360;       // 56
    float* xsp = sm4 + 26416;      // 1

    const int b = blockIdx.x, tid = threadIdx.x;
    const int w = tid >> 5, lane = tid & 31;

    {
        const float4* s1 = (const float4*)W1;
        float4* d1 = (float4*)W1s;
        for (int i = tid; i < 5000; i += 256) d1[i] = s1[i];
        const float4* s2 = (const float4*)W2;
        float4* d2 = (float4*)W2s;
        for (int i = tid; i < 1250; i += 256) d2[i] = s2[i];
        if (tid < 50) W3s[tid] = W3[tid];
    }
    if (tid < HH) {
        float s = 0.f;
#pragma unroll
        for (int c = 0; c < 8; c++) s += g_ctxp[(c * BB + b) * HH + tid];
        ctx_s[tid] = s;
    }
    if (tid == 0) xsp[0] = x0[b];
    __syncthreads();

    for (int j = tid; j < H4; j += 256) {
        const float* wr = W_ih + (size_t)j * 201 + 1;
        float s0 = 0.f, s1 = 0.f, s2 = 0.f, s3 = 0.f;
#pragma unroll 8
        for (int k = 0; k < HH; k += 4) {
            s0 = fmaf(wr[k], ctx_s[k], s0);
            s1 = fmaf(wr[k + 1], ctx_s[k + 1], s1);
            s2 = fmaf(wr[k + 2], ctx_s[k + 2], s2);
            s3 = fmaf(wr[k + 3], ctx_s[k + 3], s3);
        }
        gbase[j] = s0 + s1 + s2 + s3 + b_ih[j] + g_hpre[b * H4 + j];
    }
    __syncthreads();

    for (int step = 0; step < NSTEPS; step++) {
        float x = xsp[0];
        if (tid < HH) {
            int h = tid;
            float gi = gbase[h]       + x * W_ih[(size_t)h * 201];
            float gf = gbase[200 + h] + x * W_ih[(size_t)(200 + h) * 201];
            float gg = gbase[400 + h] + x * W_ih[(size_t)(400 + h) * 201];
            float go = gbase[600 + h] + x * W_ih[(size_t)(600 + h) * 201];
            float c_new = sigf(gf) * c0[b * HH + h] + sigf(gi) * tanhf(gg);
            hbuf[h] = fmaxf(sigf(go) * tanhf(c_new), 0.f);
        }
        __syncthreads();

        for (int o = w; o < 100; o += 8) {
            float s = 0.f;
            const float* wr = W1s + o * HH;
            for (int k = lane; k < HH; k += 32) s = fmaf(wr[k], hbuf[k], s);
            s = warp_reduce(s);
            if (lane == 0) o1[o] = fmaxf(s + b1[o], 0.f);
        }
        __syncthreads();

        for (int o = w; o < 50; o += 8) {
            float s = 0.f;
            const float* wr = W2s + o * 100;
            for (int k = lane; k < 100; k += 32) s = fmaf(wr[k], o1[k], s);
            s = warp_reduce(s);
            if (lane == 0) o2[o] = fmaxf(s + b2[o], 0.f);
        }
        __syncthreads();

        if (w == 0) {
            float s = 0.f;
            for (int k = lane; k < 50; k += 32) s = fmaf(W3s[k], o2[k], s);
            s = warp_reduce(s);
            if (lane == 0) {
                float y = s + b3[0];
                out[b * NSTEPS + step] = y;
                xsp[0] = y;
            }
        }
        __syncthreads();
    }
}

// ---------------------------------------------------------------------------
extern "C" void kernel_launch(void* const* d_in, const int* in_sizes, int n_in,
                              void* d_out, int out_size) {
    const float* x    = (const float*)d_in[0];
    const float* h0   = (const float*)d_in[1];
    const float* c0   = (const float*)d_in[2];
    const float* enc  = (const float*)d_in[3];
    const float* Wa   = (const float*)d_in[4];
    const float* ba   = (const float*)d_in[5];
    const float* Ua   = (const float*)d_in[6];
    const float* bua  = (const float*)d_in[7];
    const float* Va   = (const float*)d_in[8];
    const float* bva  = (const float*)d_in[9];
    const float* W_ih = (const float*)d_in[10];
    const float* W_hh = (const float*)d_in[11];
    const float* b_ih = (const float*)d_in[12];
    const float* b_hh = (const float*)d_in[13];
    const float* W1   = (const float*)d_in[14];
    const float* b1   = (const float*)d_in[15];
    const float* W2   = (const float*)d_in[16];
    const float* b2   = (const float*)d_in[17];
    const float* W3   = (const float*)d_in[18];
    const float* b3   = (const float*)d_in[19];
    float* out = (float*)d_out;

    cudaFuncSetAttribute(k2_scores_f2, cudaFuncAttributeMaxDynamicSharedMemorySize, S2_TOTAL);
    const int smem4 = 26420 * sizeof(float);
    cudaFuncSetAttribute(k4_decode, cudaFuncAttributeMaxDynamicSharedMemorySize, smem4);

    kP_pack_ua<<<(10400 + 255) / 256, 256>>>(Ua);
    k1_proj<<<BB, 256>>>(h0, Wa, ba, W_hh, b_hh);
    k2_scores_f2<<<dim3(TT / 128, BB), 208, S2_TOTAL>>>(enc, bua, Va, bva);
    k3a_softmax<<<BB, 256>>>();
    k3b_ctx<<<dim3(8, BB), 256>>>(enc);
    k4_decode<<<BB, 256, smem4>>>(x, c0, W_ih, b_ih, W1, b1, W2, b2, W3, b3, out);
}

// round 9
// speedup vs baseline: 1.8283x; 1.0021x over previous
#include <cuda_runtime.h>
#include <math.h>
#include <stdint.h>

#define BB 128
#define TT 2048
#define HH 200
#define H4 800
#define NSTEPS 5

// ---------------- scratch globals (no cudaMalloc allowed) ------------------
__device__ float g_qproj[BB * HH];
__device__ float g_hpre[BB * H4];
__device__ float g_scores[BB * TT];
__device__ float g_ctxp[8 * BB * HH];
// duplicated+transposed Ua: g_uad[k*200+h] = {Ua[h][k], Ua[h][k]}
__device__ __align__(16) float2 g_uad[HH * HH];

__device__ __forceinline__ float sigf(float x) { return 1.f / (1.f + expf(-x)); }

__device__ __forceinline__ float warp_reduce(float v) {
#pragma unroll
    for (int m = 16; m > 0; m >>= 1) v += __shfl_xor_sync(0xffffffffu, v, m);
    return v;
}

__device__ __forceinline__ float tanh_fast(float x) {
    // tanh(x) = 1 - 2/(e^{2x}+1), via MUFU ex2/rcp
    float e;
    asm("ex2.approx.f32 %0, %1;" : "=f"(e) : "f"(x * 2.885390081777927f));
    float r;
    asm("rcp.approx.f32 %0, %1;" : "=f"(r) : "f"(e + 1.0f));
    return fmaf(-2.f, r, 1.f);
}

__device__ __forceinline__ uint32_t smem_u32(const void* p) {
    uint32_t a;
    asm("{ .reg .u64 t; cvta.to.shared.u64 t, %1; cvt.u32.u64 %0, t; }" : "=r"(a) : "l"(p));
    return a;
}

// packed fp32x2 FMA (B300 FFMA2 — 2 MACs/lane/instr)
#define FMA2(c, a, b) \
    asm("fma.rn.f32x2 %0, %1, %2, %0;" : "+l"(c) : "l"(a), "l"(b))
#define UNPACK2(lo, hi, p) \
    asm("mov.b64 {%0, %1}, %2;" : "=f"(lo), "=f"(hi) : "l"(p))
#define LDS2U64(a, b, addr) \
    asm("ld.shared.v2.u64 {%0,%1}, [%2];" : "=l"(a), "=l"(b) : "r"(addr))

// ---------------------------------------------------------------------------
// KP: g_uad[k][h] = {Ua[h][k], Ua[h][k]}  (transpose + duplicate, one-time)
// ---------------------------------------------------------------------------
__global__ void kP_dup_ua(const float* __restrict__ Ua) {
    int i = blockIdx.x * 256 + threadIdx.x;
    if (i >= HH * HH) return;
    int k = i / HH, h = i % HH;
    float v = Ua[h * HH + k];
    g_uad[i] = make_float2(v, v);
}

// ---------------------------------------------------------------------------
// K1: q_proj[b,h] = h0[b]·Wa[h] + ba[h];  h_pre[b,j] = h0[b]·W_hh[j] + b_hh[j]
// ---------------------------------------------------------------------------
__global__ void k1_proj(const float* __restrict__ h0, const float* __restrict__ Wa,
                        const float* __restrict__ ba, const float* __restrict__ Whh,
                        const float* __restrict__ bhh) {
    int b = blockIdx.x, tid = threadIdx.x;
    __shared__ float h0s[HH];
    if (tid < HH) h0s[tid] = h0[b * HH + tid];
    __syncthreads();
    for (int j = tid; j < HH; j += blockDim.x) {
        const float4* w = (const float4*)(Wa + j * HH);
        float s0 = 0.f, s1 = 0.f, s2 = 0.f, s3 = 0.f;
#pragma unroll 5
        for (int k = 0; k < HH / 4; k++) {
            float4 wv = w[k];
            const float* hp = &h0s[k * 4];
            s0 = fmaf(wv.x, hp[0], s0); s1 = fmaf(wv.y, hp[1], s1);
            s2 = fmaf(wv.z, hp[2], s2); s3 = fmaf(wv.w, hp[3], s3);
        }
        g_qproj[b * HH + j] = s0 + s1 + s2 + s3 + ba[j];
    }
    for (int j = tid; j < H4; j += blockDim.x) {
        const float4* w = (const float4*)(Whh + j * HH);
        float s0 = 0.f, s1 = 0.f, s2 = 0.f, s3 = 0.f;
#pragma unroll 5
        for (int k = 0; k < HH / 4; k++) {
            float4 wv = w[k];
            const float* hp = &h0s[k * 4];
            s0 = fmaf(wv.x, hp[0], s0); s1 = fmaf(wv.y, hp[1], s1);
            s2 = fmaf(wv.z, hp[2], s2); s3 = fmaf(wv.w, hp[3], s3);
        }
        g_hpre[b * H4 + j] = s0 + s1 + s2 + s3 + bhh[j];
    }
}

// ---------------------------------------------------------------------------
// K2 v3: packed-fp32 (fma.rn.f32x2) fused scores kernel, conflict-free LDS.
// 400 threads: hg = tid>>4 (25 h-groups of 8h), tg = tid&15 (16 t-groups of 8t).
// Warps are uniform: 2 hg x 16 tg -> enc loads are 16 lane-contiguous 16B
// chunks (2-phase floor), ua loads 2x64B broadcast (1 phase).
// enc_T[k] row permuted: float idx = (sub>>2)*64 + tg*4 + (sub&3), sub=t&7.
// Ua pre-transposed+duplicated in g_uad; staged in 4 chunks of 50 k.
// ---------------------------------------------------------------------------
#define S2_ENC   0                        // 200*128*4 = 102400
#define S2_UA    102400                   // 50*200*8  =  80000  (f32x2 dup)
#define S2_PART  102400                   // 128*25*4  =  12800  (aliases UA)
#define S2_QPB   182400                   // 800
#define S2_VAS   183200                   // 800
#define S2_TOTAL 184000

__global__ __launch_bounds__(400, 1)
void k2_scores_f2(const float* __restrict__ enc,
                  const float* __restrict__ bua, const float* __restrict__ Va,
                  const float* __restrict__ bva) {
    extern __shared__ char smc[];
    float* enc_T = (float*)smc;
    float* part = (float*)(smc + S2_PART);
    float* qpb = (float*)(smc + S2_QPB);
    float* vas = (float*)(smc + S2_VAS);
    const uint32_t sbase = smem_u32(smc);

    const int b = blockIdx.y;
    const int t0 = blockIdx.x * 128;
    const int tid = threadIdx.x;
    const int hg = tid >> 4, tg = tid & 15;

    // ---- stage enc tile, transposed + row-permuted ----
    {
        const float* ep = enc + (size_t)(b * TT + t0) * HH;
#pragma unroll
        for (int it = 0; it < 16; it++) {
            int idx = tid + it * 400;                 // 6400 = 128t * 50 k4
            int t = idx & 127, c = idx >> 7;          // c = k/4
            float4 v = *(const float4*)(ep + (size_t)t * HH + c * 4);
            int tgg = t >> 3, sub = t & 7;
            int pos = ((sub >> 2) << 6) + (tgg << 2) + (sub & 3);
            float vv[4] = {v.x, v.y, v.z, v.w};
#pragma unroll
            for (int j = 0; j < 4; j++)
                enc_T[(c * 4 + j) * 128 + pos] = vv[j];
        }
    }
    if (tid < HH) {
        qpb[tid] = g_qproj[b * HH + tid] + bua[tid];
        vas[tid] = Va[tid];
    }

    uint64_t acc[4][8];
#pragma unroll
    for (int p = 0; p < 4; p++)
#pragma unroll
        for (int j = 0; j < 8; j++) acc[p][j] = 0ull;

    const uint32_t ebase = sbase + S2_ENC + tg * 16;
    const uint32_t ubase = sbase + S2_UA + hg * 64;

    for (int c = 0; c < 4; c++) {
        __syncthreads();
        // stage ua chunk c: 50 k x 200 h f32x2 = 80000B = 5000 uint4
        {
            const uint4* src = (const uint4*)(g_uad + c * 50 * HH);
            uint4* dst = (uint4*)(smc + S2_UA);
            for (int i = tid; i < 5000; i += 400) dst[i] = src[i];
        }
        __syncthreads();

#pragma unroll 2
        for (int kk = 0; kk < 50; kk++) {
            uint32_t ea = ebase + (c * 50 + kk) * 512;
            uint32_t ua = ubase + kk * 1600;
            uint64_t E0, E1, E2, E3;
            LDS2U64(E0, E1, ea);
            LDS2U64(E2, E3, ea + 256);
            uint64_t D0, D1, D2, D3, D4, D5, D6, D7;
            LDS2U64(D0, D1, ua);
            LDS2U64(D2, D3, ua + 16);
            LDS2U64(D4, D5, ua + 32);
            LDS2U64(D6, D7, ua + 48);
            FMA2(acc[0][0], E0, D0); FMA2(acc[1][0], E1, D0);
            FMA2(acc[2][0], E2, D0); FMA2(acc[3][0], E3, D0);
            FMA2(acc[0][1], E0, D1); FMA2(acc[1][1], E1, D1);
            FMA2(acc[2][1], E2, D1); FMA2(acc[3][1], E3, D1);
            FMA2(acc[0][2], E0, D2); FMA2(acc[1][2], E1, D2);
            FMA2(acc[2][2], E2, D2); FMA2(acc[3][2], E3, D2);
            FMA2(acc[0][3], E0, D3); FMA2(acc[1][3], E1, D3);
            FMA2(acc[2][3], E2, D3); FMA2(acc[3][3], E3, D3);
            FMA2(acc[0][4], E0, D4); FMA2(acc[1][4], E1, D4);
            FMA2(acc[2][4], E2, D4); FMA2(acc[3][4], E3, D4);
            FMA2(acc[0][5], E0, D5); FMA2(acc[1][5], E1, D5);
            FMA2(acc[2][5], E2, D5); FMA2(acc[3][5], E3, D5);
            FMA2(acc[0][6], E0, D6); FMA2(acc[1][6], E1, D6);
            FMA2(acc[2][6], E2, D6); FMA2(acc[3][6], E3, D6);
            FMA2(acc[0][7], E0, D7); FMA2(acc[1][7], E1, D7);
            FMA2(acc[2][7], E2, D7); FMA2(acc[3][7], E3, D7);
        }
    }
    __syncthreads();   // last ua reads done before part (aliased) is written

    // ---- epilogue: tanh + Va partial per t over this thread's 8 h ----
    {
        float sp[8];
#pragma unroll
        for (int s = 0; s < 8; s++) sp[s] = 0.f;
#pragma unroll
        for (int j = 0; j < 8; j++) {
            int h = hg * 8 + j;
            float vq = vas[h], qb = qpb[h];
#pragma unroll
            for (int p = 0; p < 4; p++) {
                float x, y;
                UNPACK2(x, y, acc[p][j]);
                sp[2 * p]     += vq * tanh_fast(x + qb);
                sp[2 * p + 1] += vq * tanh_fast(y + qb);
            }
        }
#pragma unroll
        for (int s = 0; s < 8; s++)
            part[(tg * 8 + s) * 25 + hg] = sp[s];
    }
    __syncthreads();

    if (tid < 128) {
        float s = bva[0];
#pragma unroll
        for (int m = 0; m < 25; m++) s += part[tid * 25 + m];
        g_scores[b * TT + t0 + tid] = s;
    }
}

// ---------------------------------------------------------------------------
// K3a: softmax over T per batch (in-place normalize g_scores)
// ---------------------------------------------------------------------------
__global__ void k3a_softmax() {
    const int b = blockIdx.x, tid = threadIdx.x;
    __shared__ float red[256];

    float lmax = -1e30f;
    for (int t = tid; t < TT; t += 256) lmax = fmaxf(lmax, g_scores[b * TT + t]);
    red[tid] = lmax;
    __syncthreads();
    for (int s = 128; s > 0; s >>= 1) {
        if (tid < s) red[tid] = fmaxf(red[tid], red[tid + s]);
        __syncthreads();
    }
    float smax = red[0];
    __syncthreads();

    float lsum = 0.f;
    for (int t = tid; t < TT; t += 256) lsum += expf(g_scores[b * TT + t] - smax);
    red[tid] = lsum;
    __syncthreads();
    for (int s = 128; s > 0; s >>= 1) {
        if (tid < s) red[tid] += red[tid + s];
        __syncthreads();
    }
    float inv = 1.f / red[0];
    __syncthreads();

    for (int t = tid; t < TT; t += 256)
        g_scores[b * TT + t] = expf(g_scores[b * TT + t] - smax) * inv;
}

// ---------------------------------------------------------------------------
// K3b: context partials (DRAM-bound, ~71% of spec)
// ---------------------------------------------------------------------------
__global__ __launch_bounds__(256)
void k3b_ctx(const float* __restrict__ enc) {
    const int ch = blockIdx.x, b = blockIdx.y, tid = threadIdx.x;
    __shared__ float atts[256];
    __shared__ float pbuf[5 * HH];

    atts[tid] = g_scores[b * TT + ch * 256 + tid];
    __syncthreads();

    const int g = tid % 50, sub = tid / 50;
    if (sub < 5) {
        float4 a = make_float4(0.f, 0.f, 0.f, 0.f);
        const float* base = enc + (size_t)(b * TT + ch * 256) * HH + g * 4;
        for (int t = sub; t < 256; t += 5) {
            float w = atts[t];
            float4 e = *(const float4*)(base + (size_t)t * HH);
            a.x = fmaf(w, e.x, a.x); a.y = fmaf(w, e.y, a.y);
            a.z = fmaf(w, e.z, a.z); a.w = fmaf(w, e.w, a.w);
        }
        *(float4*)&pbuf[sub * HH + g * 4] = a;
    }
    __syncthreads();

    if (tid < HH) {
        float s = 0.f;
#pragma unroll
        for (int u = 0; u < 5; u++) s += pbuf[u * HH + tid];
        g_ctxp[(ch * BB + b) * HH + tid] = s;
    }
}

// ---------------------------------------------------------------------------
// K4: decode (SMEM weights + warp-cooperative matvecs)
// ---------------------------------------------------------------------------
__global__ __launch_bounds__(256)
void k4_decode(const float* __restrict__ x0, const float* __restrict__ c0,
               const float* __restrict__ W_ih, const float* __restrict__ b_ih,
               const float* __restrict__ W1, const float* __restrict__ b1,
               const float* __restrict__ W2, const float* __restrict__ b2,
               const float* __restrict__ W3, const float* __restrict__ b3,
               float* __restrict__ out) {
    extern __shared__ float sm4[];
    float* W1s = sm4;              // 20000
    float* W2s = sm4 + 20000;      // 5000
    float* W3s = sm4 + 25000;      // 50
    float* ctx_s = sm4 + 25056;    // 200
    float* gbase = sm4 + 25256;    // 800
    float* hbuf = sm4 + 26056;     // 200
    float* o1 = sm4 + 26256;       // 104
    float* o2 = sm4 + 26360;       // 56
    float* xsp = sm4 + 26416;      // 1

    const int b = blockIdx.x, tid = threadIdx.x;
    const int w = tid >> 5, lane = tid & 31;

    {
        const float4* s1 = (const float4*)W1;
        float4* d1 = (float4*)W1s;
        for (int i = tid; i < 5000; i += 256) d1[i] = s1[i];
        const float4* s2 = (const float4*)W2;
        float4* d2 = (float4*)W2s;
        for (int i = tid; i < 1250; i += 256) d2[i] = s2[i];
        if (tid < 50) W3s[tid] = W3[tid];
    }
    if (tid < HH) {
        float s = 0.f;
#pragma unroll
        for (int c = 0; c < 8; c++) s += g_ctxp[(c * BB + b) * HH + tid];
        ctx_s[tid] = s;
    }
    if (tid == 0) xsp[0] = x0[b];
    __syncthreads();

    for (int j = tid; j < H4; j += 256) {
        const float* wr = W_ih + (size_t)j * 201 + 1;
        float s0 = 0.f, s1 = 0.f, s2 = 0.f, s3 = 0.f;
#pragma unroll 8
        for (int k = 0; k < HH; k += 4) {
            s0 = fmaf(wr[k], ctx_s[k], s0);
            s1 = fmaf(wr[k + 1], ctx_s[k + 1], s1);
            s2 = fmaf(wr[k + 2], ctx_s[k + 2], s2);
            s3 = fmaf(wr[k + 3], ctx_s[k + 3], s3);
        }
        gbase[j] = s0 + s1 + s2 + s3 + b_ih[j] + g_hpre[b * H4 + j];
    }
    __syncthreads();

    for (int step = 0; step < NSTEPS; step++) {
        float x = xsp[0];
        if (tid < HH) {
            int h = tid;
            float gi = gbase[h]       + x * W_ih[(size_t)h * 201];
            float gf = gbase[200 + h] + x * W_ih[(size_t)(200 + h) * 201];
            float gg = gbase[400 + h] + x * W_ih[(size_t)(400 + h) * 201];
            float go = gbase[600 + h] + x * W_ih[(size_t)(600 + h) * 201];
            float c_new = sigf(gf) * c0[b * HH + h] + sigf(gi) * tanhf(gg);
            hbuf[h] = fmaxf(sigf(go) * tanhf(c_new), 0.f);
        }
        __syncthreads();

        for (int o = w; o < 100; o += 8) {
            float s = 0.f;
            const float* wr = W1s + o * HH;
            for (int k = lane; k < HH; k += 32) s = fmaf(wr[k], hbuf[k], s);
            s = warp_reduce(s);
            if (lane == 0) o1[o] = fmaxf(s + b1[o], 0.f);
        }
        __syncthreads();

        for (int o = w; o < 50; o += 8) {
            float s = 0.f;
            const float* wr = W2s + o * 100;
            for (int k = lane; k < 100; k += 32) s = fmaf(wr[k], o1[k], s);
            s = warp_reduce(s);
            if (lane == 0) o2[o] = fmaxf(s + b2[o], 0.f);
        }
        __syncthreads();

        if (w == 0) {
            float s = 0.f;
            for (int k = lane; k < 50; k += 32) s = fmaf(W3s[k], o2[k], s);
            s = warp_reduce(s);
            if (lane == 0) {
                float y = s + b3[0];
                out[b * NSTEPS + step] = y;
                xsp[0] = y;
            }
        }
        __syncthreads();
    }
}

// ---------------------------------------------------------------------------
extern "C" void kernel_launch(void* const* d_in, const int* in_sizes, int n_in,
                              void* d_out, int out_size) {
    const float* x    = (const float*)d_in[0];
    const float* h0   = (const float*)d_in[1];
    const float* c0   = (const float*)d_in[2];
    const float* enc  = (const float*)d_in[3];
    const float* Wa   = (const float*)d_in[4];
    const float* ba   = (const float*)d_in[5];
    const float* Ua   = (const float*)d_in[6];
    const float* bua  = (const float*)d_in[7];
    const float* Va   = (const float*)d_in[8];
    const float* bva  = (const float*)d_in[9];
    const float* W_ih = (const float*)d_in[10];
    const float* W_hh = (const float*)d_in[11];
    const float* b_ih = (const float*)d_in[12];
    const float* b_hh = (const float*)d_in[13];
    const float* W1   = (const float*)d_in[14];
    const float* b1   = (const float*)d_in[15];
    const float* W2   = (const float*)d_in[16];
    const float* b2   = (const float*)d_in[17];
    const float* W3   = (const float*)d_in[18];
    const float* b3   = (const float*)d_in[19];
    float* out = (float*)d_out;

    cudaFuncSetAttribute(k2_scores_f2, cudaFuncAttributeMaxDynamicSharedMemorySize, S2_TOTAL);
    const int smem4 = 26420 * sizeof(float);
    cudaFuncSetAttribute(k4_decode, cudaFuncAttributeMaxDynamicSharedMemorySize, smem4);

    kP_dup_ua<<<(HH * HH + 255) / 256, 256>>>(Ua);
    k1_proj<<<BB, 256>>>(h0, Wa, ba, W_hh, b_hh);
    k2_scores_f2<<<dim3(TT / 128, BB), 400, S2_TOTAL>>>(enc, bua, Va, bva);
    k3a_softmax<<<BB, 256>>>();
    k3b_ctx<<<dim3(8, BB), 256>>>(enc);
    k4_decode<<<BB, 256, smem4>>>(x, c0, W_ih, b_ih, W1, b1, W2, b2, W3, b3, out);
}

// round 10
// speedup vs baseline: 2.1477x; 1.1747x over previous
#include <cuda_runtime.h>
#include <math.h>
#include <stdint.h>

#define BB 128
#define TT 2048
#define HH 200
#define H4 800
#define NSTEPS 5

// ---------------- scratch globals (no cudaMalloc allowed) ------------------
__device__ float g_qproj[BB * HH];
__device__ float g_hpre[BB * H4];
__device__ float g_scores[BB * TT];
__device__ float g_ctxp[8 * BB * HH];
// duplicated+transposed Ua: g_uad[k*200+h] = {Ua[h][k], Ua[h][k]}
__device__ __align__(16) float2 g_uad[HH * HH];

__device__ __forceinline__ float sigf(float x) { return 1.f / (1.f + expf(-x)); }

__device__ __forceinline__ float warp_reduce(float v) {
#pragma unroll
    for (int m = 16; m > 0; m >>= 1) v += __shfl_xor_sync(0xffffffffu, v, m);
    return v;
}

__device__ __forceinline__ float tanh_fast(float x) {
    float e;
    asm("ex2.approx.f32 %0, %1;" : "=f"(e) : "f"(x * 2.885390081777927f));
    float r;
    asm("rcp.approx.f32 %0, %1;" : "=f"(r) : "f"(e + 1.0f));
    return fmaf(-2.f, r, 1.f);
}

__device__ __forceinline__ uint32_t smem_u32(const void* p) {
    uint32_t a;
    asm("{ .reg .u64 t; cvta.to.shared.u64 t, %1; cvt.u32.u64 %0, t; }" : "=r"(a) : "l"(p));
    return a;
}

// packed fp32x2 FMA (B300 FFMA2 — 2 MACs/lane/instr)
#define FMA2(c, a, b) \
    asm("fma.rn.f32x2 %0, %1, %2, %0;" : "+l"(c) : "l"(a), "l"(b))
#define UNPACK2(lo, hi, p) \
    asm("mov.b64 {%0, %1}, %2;" : "=f"(lo), "=f"(hi) : "l"(p))
#define LDS2U64(a, b, addr) \
    asm("ld.shared.v2.u64 {%0,%1}, [%2];" : "=l"(a), "=l"(b) : "r"(addr))
#define CPASYNC16(dst, src) \
    asm volatile("cp.async.cg.shared.global [%0], [%1], 16;" :: "r"(dst), "l"(src))
#define CPCOMMIT() asm volatile("cp.async.commit_group;" ::: "memory")
#define CPWAIT0() asm volatile("cp.async.wait_group 0;" ::: "memory")

// ---------------------------------------------------------------------------
// KD: no-op alignment kernel (makes k2 the 4th launch -> ncu captures k2)
// ---------------------------------------------------------------------------
__global__ void kD_align() {}

// ---------------------------------------------------------------------------
// KP: g_uad[k][h] = {Ua[h][k], Ua[h][k]}  (transpose + duplicate, one-time)
// ---------------------------------------------------------------------------
__global__ void kP_dup_ua(const float* __restrict__ Ua) {
    int i = blockIdx.x * 256 + threadIdx.x;
    if (i >= HH * HH) return;
    int k = i / HH, h = i % HH;
    float v = Ua[h * HH + k];
    g_uad[i] = make_float2(v, v);
}

// ---------------------------------------------------------------------------
// K1: q_proj[b,h] = h0[b]·Wa[h] + ba[h];  h_pre[b,j] = h0[b]·W_hh[j] + b_hh[j]
// ---------------------------------------------------------------------------
__global__ void k1_proj(const float* __restrict__ h0, const float* __restrict__ Wa,
                        const float* __restrict__ ba, const float* __restrict__ Whh,
                        const float* __restrict__ bhh) {
    int b = blockIdx.x, tid = threadIdx.x;
    __shared__ float h0s[HH];
    if (tid < HH) h0s[tid] = h0[b * HH + tid];
    __syncthreads();
    for (int j = tid; j < HH; j += blockDim.x) {
        const float4* w = (const float4*)(Wa + j * HH);
        float s0 = 0.f, s1 = 0.f, s2 = 0.f, s3 = 0.f;
#pragma unroll 5
        for (int k = 0; k < HH / 4; k++) {
            float4 wv = w[k];
            const float* hp = &h0s[k * 4];
            s0 = fmaf(wv.x, hp[0], s0); s1 = fmaf(wv.y, hp[1], s1);
            s2 = fmaf(wv.z, hp[2], s2); s3 = fmaf(wv.w, hp[3], s3);
        }
        g_qproj[b * HH + j] = s0 + s1 + s2 + s3 + ba[j];
    }
    for (int j = tid; j < H4; j += blockDim.x) {
        const float4* w = (const float4*)(Whh + j * HH);
        float s0 = 0.f, s1 = 0.f, s2 = 0.f, s3 = 0.f;
#pragma unroll 5
        for (int k = 0; k < HH / 4; k++) {
            float4 wv = w[k];
            const float* hp = &h0s[k * 4];
            s0 = fmaf(wv.x, hp[0], s0); s1 = fmaf(wv.y, hp[1], s1);
            s2 = fmaf(wv.z, hp[2], s2); s3 = fmaf(wv.w, hp[3], s3);
        }
        g_hpre[b * H4 + j] = s0 + s1 + s2 + s3 + bhh[j];
    }
}

// ---------------------------------------------------------------------------
// K2 v4: packed-fp32 (fma.rn.f32x2) fused scores kernel.
// Same conflict-free inner loop as v3 (400 threads, hg=tid>>4, tg=tid&15,
// enc transposed+permuted, Ua pre-dup'd) but Ua staged via cp.async in 8
// double-buffered chunks of 25 k, fully overlapped with compute; part buffer
// no longer aliases Ua.
// ---------------------------------------------------------------------------
#define S2_ENC   0                        // 200*128*4 = 102400
#define S2_UA    102400                   // 2 bufs x 25k*200h*8B = 80000
#define S2_PART  182400                   // 128*25*4  =  12800
#define S2_QPB   195200                   // 800
#define S2_VAS   196000                   // 800
#define S2_TOTAL 196800
#define UA_BUF   40000                    // bytes per 25-k chunk

__global__ __launch_bounds__(400, 1)
void k2_scores_f2(const float* __restrict__ enc,
                  const float* __restrict__ bua, const float* __restrict__ Va,
                  const float* __restrict__ bva) {
    extern __shared__ char smc[];
    float* enc_T = (float*)smc;
    float* part = (float*)(smc + S2_PART);
    float* qpb = (float*)(smc + S2_QPB);
    float* vas = (float*)(smc + S2_VAS);
    const uint32_t sbase = smem_u32(smc);

    const int b = blockIdx.y;
    const int t0 = blockIdx.x * 128;
    const int tid = threadIdx.x;
    const int hg = tid >> 4, tg = tid & 15;

    // ---- prefetch Ua chunk 0 via cp.async (overlaps with enc staging) ----
    {
        const char* src = (const char*)(g_uad);
        uint32_t dst = sbase + S2_UA;
        for (int i = tid; i < 2500; i += 400)
            CPASYNC16(dst + i * 16, src + i * 16);
        CPCOMMIT();
    }

    // ---- stage enc tile, transposed + row-permuted ----
    {
        const float* ep = enc + (size_t)(b * TT + t0) * HH;
#pragma unroll
        for (int it = 0; it < 16; it++) {
            int idx = tid + it * 400;                 // 6400 = 128t * 50 k4
            int t = idx & 127, c = idx >> 7;          // c = k/4
            float4 v = *(const float4*)(ep + (size_t)t * HH + c * 4);
            int tgg = t >> 3, sub = t & 7;
            int pos = ((sub >> 2) << 6) + (tgg << 2) + (sub & 3);
            float vv[4] = {v.x, v.y, v.z, v.w};
#pragma unroll
            for (int j = 0; j < 4; j++)
                enc_T[(c * 4 + j) * 128 + pos] = vv[j];
        }
    }
    if (tid < HH) {
        qpb[tid] = g_qproj[b * HH + tid] + bua[tid];
        vas[tid] = Va[tid];
    }

    uint64_t acc[4][8];
#pragma unroll
    for (int p = 0; p < 4; p++)
#pragma unroll
        for (int j = 0; j < 8; j++) acc[p][j] = 0ull;

    const uint32_t ebase = sbase + S2_ENC + tg * 16;

    for (int c = 0; c < 8; c++) {
        CPWAIT0();            // chunk c resident in buf[c&1]
        __syncthreads();
        if (c < 7) {          // prefetch chunk c+1 into buf[(c+1)&1]
            const char* src = (const char*)(g_uad + (c + 1) * 25 * HH);
            uint32_t dst = sbase + S2_UA + ((c + 1) & 1) * UA_BUF;
            for (int i = tid; i < 2500; i += 400)
                CPASYNC16(dst + i * 16, src + i * 16);
            CPCOMMIT();
        }

        const uint32_t ubase = sbase + S2_UA + (c & 1) * UA_BUF + hg * 64;
#pragma unroll
        for (int kk = 0; kk < 25; kk++) {
            uint32_t ea = ebase + (c * 25 + kk) * 512;
            uint32_t ua = ubase + kk * 1600;
            uint64_t E0, E1, E2, E3;
            LDS2U64(E0, E1, ea);
            LDS2U64(E2, E3, ea + 256);
            uint64_t D0, D1, D2, D3, D4, D5, D6, D7;
            LDS2U64(D0, D1, ua);
            LDS2U64(D2, D3, ua + 16);
            LDS2U64(D4, D5, ua + 32);
            LDS2U64(D6, D7, ua + 48);
            FMA2(acc[0][0], E0, D0); FMA2(acc[1][0], E1, D0);
            FMA2(acc[2][0], E2, D0); FMA2(acc[3][0], E3, D0);
            FMA2(acc[0][1], E0, D1); FMA2(acc[1][1], E1, D1);
            FMA2(acc[2][1], E2, D1); FMA2(acc[3][1], E3, D1);
            FMA2(acc[0][2], E0, D2); FMA2(acc[1][2], E1, D2);
            FMA2(acc[2][2], E2, D2); FMA2(acc[3][2], E3, D2);
            FMA2(acc[0][3], E0, D3); FMA2(acc[1][3], E1, D3);
            FMA2(acc[2][3], E2, D3); FMA2(acc[3][3], E3, D3);
            FMA2(acc[0][4], E0, D4); FMA2(acc[1][4], E1, D4);
            FMA2(acc[2][4], E2, D4); FMA2(acc[3][4], E3, D4);
            FMA2(acc[0][5], E0, D5); FMA2(acc[1][5], E1, D5);
            FMA2(acc[2][5], E2, D5); FMA2(acc[3][5], E3, D5);
            FMA2(acc[0][6], E0, D6); FMA2(acc[1][6], E1, D6);
            FMA2(acc[2][6], E2, D6); FMA2(acc[3][6], E3, D6);
            FMA2(acc[0][7], E0, D7); FMA2(acc[1][7], E1, D7);
            FMA2(acc[2][7], E2, D7); FMA2(acc[3][7], E3, D7);
        }
        // no trailing sync: next iter's CPWAIT0+syncthreads orders reuse
    }

    // ---- epilogue: tanh + Va partial per t over this thread's 8 h ----
    {
        float sp[8];
#pragma unroll
        for (int s = 0; s < 8; s++) sp[s] = 0.f;
#pragma unroll
        for (int j = 0; j < 8; j++) {
            int h = hg * 8 + j;
            float vq = vas[h], qb = qpb[h];
#pragma unroll
            for (int p = 0; p < 4; p++) {
                float x, y;
                UNPACK2(x, y, acc[p][j]);
                sp[2 * p]     += vq * tanh_fast(x + qb);
                sp[2 * p + 1] += vq * tanh_fast(y + qb);
            }
        }
#pragma unroll
        for (int s = 0; s < 8; s++)
            part[(tg * 8 + s) * 25 + hg] = sp[s];
    }
    __syncthreads();

    if (tid < 128) {
        float s = bva[0];
#pragma unroll
        for (int m = 0; m < 25; m++) s += part[tid * 25 + m];
        g_scores[b * TT + t0 + tid] = s;
    }
}

// ---------------------------------------------------------------------------
// K3a: softmax over T per batch (in-place normalize g_scores)
// ---------------------------------------------------------------------------
__global__ void k3a_softmax() {
    const int b = blockIdx.x, tid = threadIdx.x;
    __shared__ float red[256];

    float lmax = -1e30f;
    for (int t = tid; t < TT; t += 256) lmax = fmaxf(lmax, g_scores[b * TT + t]);
    red[tid] = lmax;
    __syncthreads();
    for (int s = 128; s > 0; s >>= 1) {
        if (tid < s) red[tid] = fmaxf(red[tid], red[tid + s]);
        __syncthreads();
    }
    float smax = red[0];
    __syncthreads();

    float lsum = 0.f;
    for (int t = tid; t < TT; t += 256) lsum += expf(g_scores[b * TT + t] - smax);
    red[tid] = lsum;
    __syncthreads();
    for (int s = 128; s > 0; s >>= 1) {
        if (tid < s) red[tid] += red[tid + s];
        __syncthreads();
    }
    float inv = 1.f / red[0];
    __syncthreads();

    for (int t = tid; t < TT; t += 256)
        g_scores[b * TT + t] = expf(g_scores[b * TT + t] - smax) * inv;
}

// ---------------------------------------------------------------------------
// K3b: context partials (DRAM-bound, ~71% of spec)
// ---------------------------------------------------------------------------
__global__ __launch_bounds__(256)
void k3b_ctx(const float* __restrict__ enc) {
    const int ch = blockIdx.x, b = blockIdx.y, tid = threadIdx.x;
    __shared__ float atts[256];
    __shared__ float pbuf[5 * HH];

    atts[tid] = g_scores[b * TT + ch * 256 + tid];
    __syncthreads();

    const int g = tid % 50, sub = tid / 50;
    if (sub < 5) {
        float4 a = make_float4(0.f, 0.f, 0.f, 0.f);
        const float* base = enc + (size_t)(b * TT + ch * 256) * HH + g * 4;
        for (int t = sub; t < 256; t += 5) {
            float w = atts[t];
            float4 e = *(const float4*)(base + (size_t)t * HH);
            a.x = fmaf(w, e.x, a.x); a.y = fmaf(w, e.y, a.y);
            a.z = fmaf(w, e.z, a.z); a.w = fmaf(w, e.w, a.w);
        }
        *(float4*)&pbuf[sub * HH + g * 4] = a;
    }
    __syncthreads();

    if (tid < HH) {
        float s = 0.f;
#pragma unroll
        for (int u = 0; u < 5; u++) s += pbuf[u * HH + tid];
        g_ctxp[(ch * BB + b) * HH + tid] = s;
    }
}

// ---------------------------------------------------------------------------
// K4: decode (SMEM weights + warp-cooperative matvecs)
// ---------------------------------------------------------------------------
__global__ __launch_bounds__(256)
void k4_decode(const float* __restrict__ x0, const float* __restrict__ c0,
               const float* __restrict__ W_ih, const float* __restrict__ b_ih,
               const float* __restrict__ W1, const float* __restrict__ b1,
               const float* __restrict__ W2, const float* __restrict__ b2,
               const float* __restrict__ W3, const float* __restrict__ b3,
               float* __restrict__ out) {
    extern __shared__ float sm4[];
    float* W1s = sm4;              // 20000
    float* W2s = sm4 + 20000;      // 5000
    float* W3s = sm4 + 25000;      // 50
    float* ctx_s = sm4 + 25056;    // 200
    float* gbase = sm4 + 25256;    // 800
    float* hbuf = sm4 + 26056;     // 200
    float* o1 = sm4 + 26256;       // 104
    float* o2 = sm4 + 26360;       // 56
    float* xsp = sm4 + 26416;      // 1

    const int b = blockIdx.x, tid = threadIdx.x;
    const int w = tid >> 5, lane = tid & 31;

    {
        const float4* s1 = (const float4*)W1;
        float4* d1 = (float4*)W1s;
        for (int i = tid; i < 5000; i += 256) d1[i] = s1[i];
        const float4* s2 = (const float4*)W2;
        float4* d2 = (float4*)W2s;
        for (int i = tid; i < 1250; i += 256) d2[i] = s2[i];
        if (tid < 50) W3s[tid] = W3[tid];
    }
    if (tid < HH) {
        float s = 0.f;
#pragma unroll
        for (int c = 0; c < 8; c++) s += g_ctxp[(c * BB + b) * HH + tid];
        ctx_s[tid] = s;
    }
    if (tid == 0) xsp[0] = x0[b];
    __syncthreads();

    for (int j = tid; j < H4; j += 256) {
        const float* wr = W_ih + (size_t)j * 201 + 1;
        float s0 = 0.f, s1 = 0.f, s2 = 0.f, s3 = 0.f;
#pragma unroll 8
        for (int k = 0; k < HH; k += 4) {
            s0 = fmaf(wr[k], ctx_s[k], s0);
            s1 = fmaf(wr[k + 1], ctx_s[k + 1], s1);
            s2 = fmaf(wr[k + 2], ctx_s[k + 2], s2);
            s3 = fmaf(wr[k + 3], ctx_s[k + 3], s3);
        }
        gbase[j] = s0 + s1 + s2 + s3 + b_ih[j] + g_hpre[b * H4 + j];
    }
    __syncthreads();

    for (int step = 0; step < NSTEPS; step++) {
        float x = xsp[0];
        if (tid < HH) {
            int h = tid;
            float gi = gbase[h]       + x * W_ih[(size_t)h * 201];
            float gf = gbase[200 + h] + x * W_ih[(size_t)(200 + h) * 201];
            float gg = gbase[400 + h] + x * W_ih[(size_t)(400 + h) * 201];
            float go = gbase[600 + h] + x * W_ih[(size_t)(600 + h) * 201];
            float c_new = sigf(gf) * c0[b * HH + h] + sigf(gi) * tanhf(gg);
            hbuf[h] = fmaxf(sigf(go) * tanhf(c_new), 0.f);
        }
        __syncthreads();

        for (int o = w; o < 100; o += 8) {
            float s = 0.f;
            const float* wr = W1s + o * HH;
            for (int k = lane; k < HH; k += 32) s = fmaf(wr[k], hbuf[k], s);
            s = warp_reduce(s);
            if (lane == 0) o1[o] = fmaxf(s + b1[o], 0.f);
        }
        __syncthreads();

        for (int o = w; o < 50; o += 8) {
            float s = 0.f;
            const float* wr = W2s + o * 100;
            for (int k = lane; k < 100; k += 32) s = fmaf(wr[k], o1[k], s);
            s = warp_reduce(s);
            if (lane == 0) o2[o] = fmaxf(s + b2[o], 0.f);
        }
        __syncthreads();

        if (w == 0) {
            float s = 0.f;
            for (int k = lane; k < 50; k += 32) s = fmaf(W3s[k], o2[k], s);
            s = warp_reduce(s);
            if (lane == 0) {
                float y = s + b3[0];
                out[b * NSTEPS + step] = y;
                xsp[0] = y;
            }
        }
        __syncthreads();
    }
}

// ---------------------------------------------------------------------------
extern "C" void kernel_launch(void* const* d_in, const int* in_sizes, int n_in,
                              void* d_out, int out_size) {
    const float* x    = (const float*)d_in[0];
    const float* h0   = (const float*)d_in[1];
    const float* c0   = (const float*)d_in[2];
    const float* enc  = (const float*)d_in[3];
    const float* Wa   = (const float*)d_in[4];
    const float* ba   = (const float*)d_in[5];
    const float* Ua   = (const float*)d_in[6];
    const float* bua  = (const float*)d_in[7];
    const float* Va   = (const float*)d_in[8];
    const float* bva  = (const float*)d_in[9];
    const float* W_ih = (const float*)d_in[10];
    const float* W_hh = (const float*)d_in[11];
    const float* b_ih = (const float*)d_in[12];
    const float* b_hh = (const float*)d_in[13];
    const float* W1   = (const float*)d_in[14];
    const float* b1   = (const float*)d_in[15];
    const float* W2   = (const float*)d_in[16];
    const float* b2   = (const float*)d_in[17];
    const float* W3   = (const float*)d_in[18];
    const float* b3   = (const float*)d_in[19];
    float* out = (float*)d_out;

    cudaFuncSetAttribute(k2_scores_f2, cudaFuncAttributeMaxDynamicSharedMemorySize, S2_TOTAL);
    const int smem4 = 26420 * sizeof(float);
    cudaFuncSetAttribute(k4_decode, cudaFuncAttributeMaxDynamicSharedMemorySize, smem4);

    // launch order arranged so k2 is the 4th launch (ncu captures launch #4)
    kP_dup_ua<<<(HH * HH + 255) / 256, 256>>>(Ua);          // 1
    k1_proj<<<BB, 256>>>(h0, Wa, ba, W_hh, b_hh);           // 2
    kD_align<<<1, 32>>>();                                  // 3 (no-op)
    k2_scores_f2<<<dim3(TT / 128, BB), 400, S2_TOTAL>>>(enc, bua, Va, bva);  // 4
    k3a_softmax<<<BB, 256>>>();                             // 5
    k3b_ctx<<<dim3(8, BB), 256>>>(enc);                     // 6
    k4_decode<<<BB, 256, smem4>>>(x, c0, W_ih, b_ih, W1, b1, W2, b2, W3, b3, out);  // 7
}